// round 9
// baseline (speedup 1.0000x reference)
#include <cuda_runtime.h>

#define NSTATE 64

typedef unsigned long long u64;

__device__ __forceinline__ u64 add2(u64 a, u64 b) {
    u64 d; asm("add.rn.f32x2 %0,%1,%2;" : "=l"(d) : "l"(a), "l"(b)); return d;
}
__device__ __forceinline__ u64 mul2(u64 a, u64 b) {
    u64 d; asm("mul.rn.f32x2 %0,%1,%2;" : "=l"(d) : "l"(a), "l"(b)); return d;
}
__device__ __forceinline__ u64 ffma2(u64 a, u64 b, u64 c) {
    u64 d; asm("fma.rn.f32x2 %0,%1,%2,%3;" : "=l"(d) : "l"(a), "l"(b), "l"(c)); return d;
}
__device__ __forceinline__ u64 pk2(float x, float y) {
    u64 r; asm("mov.b64 %0,{%1,%2};" : "=l"(r) : "f"(x), "f"(y)); return r;
}
__device__ __forceinline__ void upk2(u64 a, float& x, float& y) {
    asm("mov.b64 {%0,%1},%2;" : "=f"(x), "=f"(y) : "l"(a));
}
__device__ __forceinline__ float rcpa(float x) {
    float r; asm("rcp.approx.f32 %0,%1;" : "=f"(r) : "f"(x)); return r;
}

// smem rows: 0:-Li 1:Lr^2 2:-Lr 3:+Lr
//            4:v00r 5:v00i 6:v01r 7:v01i 8:v10r 9:v10i 10:v11r 11:v11i
__global__ __launch_bounds__(128) void s4_cauchy_kernel(
    const float* __restrict__ Lr, const float* __restrict__ Li,
    const float* __restrict__ Pr, const float* __restrict__ Pi,
    const float* __restrict__ Qr, const float* __restrict__ Qi,
    const float* __restrict__ Br, const float* __restrict__ Bi,
    const float* __restrict__ Cr, const float* __restrict__ Ci,
    const float* __restrict__ step_ptr,
    float* __restrict__ out, int L)
{
    __shared__ __align__(16) float sQ[12][NSTATE];
    __shared__ float sStep;

    const int t = threadIdx.x;
    if (t == 0) sStep = step_ptr[0];
    if (t < NSTATE) {
        float lr = Lr[t], li = Li[t];
        float cr = Cr[t], ci = Ci[t];
        float qr = Qr[t], qi = Qi[t];
        float br = Br[t], bi = Bi[t];
        float pr = Pr[t], pi = Pi[t];
        // v00 = conj(C)*B, v01 = conj(C)*P, v10 = conj(Q)*B, v11 = conj(Q)*P
        sQ[0][t]  = -li;
        sQ[1][t]  = lr * lr;
        sQ[2][t]  = -lr;
        sQ[3][t]  =  lr;
        sQ[4][t]  = cr * br + ci * bi;  sQ[5][t]  = cr * bi - ci * br;
        sQ[6][t]  = cr * pr + ci * pi;  sQ[7][t]  = cr * pi - ci * pr;
        sQ[8][t]  = qr * br + qi * bi;  sQ[9][t]  = qr * bi - qi * br;
        sQ[10][t] = qr * pr + qi * pi;  sQ[11][t] = qr * pi - qi * pr;
    }
    __syncthreads();

    // Two frequencies per thread: k0 and k1 = k0 + 128.
    const int k0 = blockIdx.x * 256 + t;
    const int k1 = k0 + 128;

    // g = i*(2/step)*tan(pi*k/L)  (purely imaginary), c = 1 + i*u, u = tan(..)
    const float PI = 3.14159265358979323846f;
    const float tos = 2.0f / sStep;
    float sn0, cs0, sn1, cs1;
    sincosf(PI * ((float)k0 / (float)L), &sn0, &cs0);
    sincosf(PI * ((float)k1 / (float)L), &sn1, &cs1);
    float u0 = __fdividef(sn0, cs0);
    float u1 = __fdividef(sn1, cs1);
    const u64 g0 = pk2(tos * u0, tos * u0);
    const u64 g1 = pk2(tos * u1, tos * u1);

    // Packed accumulators for both k's. Imag parts accumulate NEGATED.
    u64 A00r = 0, A00i = 0, A01r = 0, A01i = 0;
    u64 A10r = 0, A10i = 0, A11r = 0, A11i = 0;
    u64 B00r = 0, B00i = 0, B01r = 0, B01i = 0;
    u64 B10r = 0, B10i = 0, B11r = 0, B11i = 0;

#define BODY(H, GG, S)                                                        \
    do {                                                                      \
        u64 di = add2(GG, nli.H);           /* di = gi - Li            */     \
        u64 m  = ffma2(di, di, lr2.H);      /* m = Lr^2 + di^2         */     \
        float m0, m1; upk2(m, m0, m1);                                        \
        u64 rr  = pk2(rcpa(m0), rcpa(m1));                                    \
        u64 ir  = mul2(nlr.H, rr);          /* Re(1/d) = -Lr/|d|^2     */     \
        u64 mir = mul2(plr.H, rr);          /* -ir                     */     \
        u64 tt  = mul2(di, rr);             /* -Im(1/d)                */     \
        S##00r = ffma2(w00r.H, ir,  S##00r); S##00r = ffma2(w00i.H, tt, S##00r); \
        S##00i = ffma2(w00i.H, mir, S##00i); S##00i = ffma2(w00r.H, tt, S##00i); \
        S##01r = ffma2(w01r.H, ir,  S##01r); S##01r = ffma2(w01i.H, tt, S##01r); \
        S##01i = ffma2(w01i.H, mir, S##01i); S##01i = ffma2(w01r.H, tt, S##01i); \
        S##10r = ffma2(w10r.H, ir,  S##10r); S##10r = ffma2(w10i.H, tt, S##10r); \
        S##10i = ffma2(w10i.H, mir, S##10i); S##10i = ffma2(w10r.H, tt, S##10i); \
        S##11r = ffma2(w11r.H, ir,  S##11r); S##11r = ffma2(w11i.H, tt, S##11r); \
        S##11i = ffma2(w11i.H, mir, S##11i); S##11i = ffma2(w11r.H, tt, S##11i); \
    } while (0)

#pragma unroll 4
    for (int p = 0; p < NSTATE / 4; p++) {
        ulonglong2 nli  = ((const ulonglong2*)sQ[0])[p];
        ulonglong2 lr2  = ((const ulonglong2*)sQ[1])[p];
        ulonglong2 nlr  = ((const ulonglong2*)sQ[2])[p];
        ulonglong2 plr  = ((const ulonglong2*)sQ[3])[p];
        ulonglong2 w00r = ((const ulonglong2*)sQ[4])[p];
        ulonglong2 w00i = ((const ulonglong2*)sQ[5])[p];
        ulonglong2 w01r = ((const ulonglong2*)sQ[6])[p];
        ulonglong2 w01i = ((const ulonglong2*)sQ[7])[p];
        ulonglong2 w10r = ((const ulonglong2*)sQ[8])[p];
        ulonglong2 w10i = ((const ulonglong2*)sQ[9])[p];
        ulonglong2 w11r = ((const ulonglong2*)sQ[10])[p];
        ulonglong2 w11i = ((const ulonglong2*)sQ[11])[p];
        BODY(x, g0, A);
        BODY(x, g1, B);
        BODY(y, g0, A);
        BODY(y, g1, B);
    }
#undef BODY

#define FINISH(S, U, DEST_OK, DEST_IDX)                                       \
    do {                                                                      \
        float x0, x1;                                                         \
        upk2(S##00r, x0, x1); float k00r =   x0 + x1;                         \
        upk2(S##00i, x0, x1); float k00i = -(x0 + x1);                        \
        upk2(S##01r, x0, x1); float k01r =   x0 + x1;                         \
        upk2(S##01i, x0, x1); float k01i = -(x0 + x1);                        \
        upk2(S##10r, x0, x1); float k10r =   x0 + x1;                         \
        upk2(S##10i, x0, x1); float k10i = -(x0 + x1);                        \
        upk2(S##11r, x0, x1); float k11r =   x0 + x1;                         \
        upk2(S##11i, x0, x1); float k11i = -(x0 + x1);                        \
        float tr = k01r * k10r - k01i * k10i;                                 \
        float ti = k01r * k10i + k01i * k10r;                                 \
        float er = 1.0f + k11r, ei = k11i;                                    \
        float rinv = __fdividef(1.0f, er * er + ei * ei);                     \
        float sr = (tr * er + ti * ei) * rinv;                                \
        float si = (ti * er - tr * ei) * rinv;                                \
        float ar = k00r - sr, ai = k00i - si;                                 \
        if (DEST_OK) out[DEST_IDX] = ar - (U) * ai; /* Re((1+iu)*(ar+i ai)) */\
    } while (0)

    FINISH(A, u0, (k0 < L), k0);
    FINISH(B, u1, (k1 < L), k1);
#undef FINISH
}

extern "C" void kernel_launch(void* const* d_in, const int* in_sizes, int n_in,
                              void* d_out, int out_size) {
    const float* Lr = (const float*)d_in[0];
    const float* Li = (const float*)d_in[1];
    const float* Pr = (const float*)d_in[2];
    const float* Pi = (const float*)d_in[3];
    const float* Qr = (const float*)d_in[4];
    const float* Qi = (const float*)d_in[5];
    const float* Br = (const float*)d_in[6];
    const float* Bi = (const float*)d_in[7];
    const float* Cr = (const float*)d_in[8];
    const float* Ci = (const float*)d_in[9];
    const float* step = (const float*)d_in[10];

    int L = out_size;  // L float32 elements = Re(atRoots)

    int threads = 128;
    int kPerBlock = 256;  // 2 frequencies per thread
    int blocks = (L + kPerBlock - 1) / kPerBlock;
    s4_cauchy_kernel<<<blocks, threads>>>(Lr, Li, Pr, Pi, Qr, Qi, Br, Bi,
                                          Cr, Ci, step, (float*)d_out, L);
}

// round 10
// speedup vs baseline: 1.1050x; 1.1050x over previous
#include <cuda_runtime.h>

#define NSTATE 64
#define NPAIR  (NSTATE / 2)

__device__ __forceinline__ float rcpa(float x) {
    float r; asm("rcp.approx.f32 %0,%1;" : "=f"(r) : "f"(x)); return r;
}

// Pairwise-fused Cauchy kernel.
//   wa/(g-la) + wb/(g-lb) = (beta*g + alpha) / (g^2 - s*g + p)
// with g = i*x purely imaginary:
//   D  = (p_r + s_i*x - x^2) + i*(p_i - s_r*x)
//   N  = (a_r - b_i*x)       + i*(a_i + b_r*x)
// smem per pair: sD = {p_r, s_i, p_i, -s_r}
//                sN[ij] = {a_r, -b_i, a_i, b_r}
__global__ __launch_bounds__(256) void s4_cauchy_kernel(
    const float* __restrict__ Lr, const float* __restrict__ Li,
    const float* __restrict__ Pr, const float* __restrict__ Pi,
    const float* __restrict__ Qr, const float* __restrict__ Qi,
    const float* __restrict__ Br, const float* __restrict__ Bi,
    const float* __restrict__ Cr, const float* __restrict__ Ci,
    const float* __restrict__ step_ptr,
    float* __restrict__ out, int L)
{
    __shared__ __align__(16) float4 sD[NPAIR];
    __shared__ __align__(16) float4 sN0[NPAIR], sN1[NPAIR], sN2[NPAIR], sN3[NPAIR];
    __shared__ float sStep;

    const int t = threadIdx.x;
    if (t == 0) sStep = step_ptr[0];
    if (t < NPAIR) {
        const int a = 2 * t, b = 2 * t + 1;
        float lar = Lr[a], lai = Li[a], lbr = Lr[b], lbi = Li[b];

        // per-state numerators w_ij = a_i * b_j  (a0=conj C, a1=conj Q; b0=B, b1=P)
        float w[2][4][2];  // [state][ij][re/im]
        for (int sidx = 0; sidx < 2; sidx++) {
            int n = (sidx == 0) ? a : b;
            float cr = Cr[n], ci = Ci[n];
            float qr = Qr[n], qi = Qi[n];
            float br = Br[n], bi = Bi[n];
            float pr = Pr[n], pi = Pi[n];
            w[sidx][0][0] = cr * br + ci * bi;  w[sidx][0][1] = cr * bi - ci * br; // conjC*B
            w[sidx][1][0] = cr * pr + ci * pi;  w[sidx][1][1] = cr * pi - ci * pr; // conjC*P
            w[sidx][2][0] = qr * br + qi * bi;  w[sidx][2][1] = qr * bi - qi * br; // conjQ*B
            w[sidx][3][0] = qr * pr + qi * pi;  w[sidx][3][1] = qr * pi - qi * pr; // conjQ*P
        }

        // s = la + lb, p = la*lb
        float s_r = lar + lbr, s_i = lai + lbi;
        float p_r = lar * lbr - lai * lbi;
        float p_i = lar * lbi + lai * lbr;
        sD[t] = make_float4(p_r, s_i, p_i, -s_r);

        float4* outN[4] = { sN0, sN1, sN2, sN3 };
        for (int ij = 0; ij < 4; ij++) {
            float war = w[0][ij][0], wai = w[0][ij][1];
            float wbr = w[1][ij][0], wbi = w[1][ij][1];
            // beta = wa + wb ; alpha = -(wa*lb + wb*la)
            float b_r = war + wbr, b_i = wai + wbi;
            float a_r = -(war * lbr - wai * lbi + wbr * lar - wbi * lai);
            float a_i = -(war * lbi + wai * lbr + wbr * lai + wbi * lar);
            outN[ij][t] = make_float4(a_r, -b_i, a_i, b_r);
        }
    }
    __syncthreads();

    const int k = blockIdx.x * blockDim.x + t;

    // x = gi = (2/step)*tan(pi*k/L);  c = 1 + i*u, u = tan(pi*k/L)
    const float PI = 3.14159265358979323846f;
    float sn, cs;
    sincosf(PI * ((float)k / (float)L), &sn, &cs);
    float u  = __fdividef(sn, cs);
    float x  = (2.0f / sStep) * u;
    float x2 = x * x;

    float k00r = 0.f, k00i = 0.f, k01r = 0.f, k01i = 0.f;
    float k10r = 0.f, k10i = 0.f, k11r = 0.f, k11i = 0.f;

#pragma unroll 8
    for (int n = 0; n < NPAIR; n++) {
        float4 d = sD[n];
        float dr = fmaf(d.y, x, d.x) - x2;   // p_r + s_i*x - x^2
        float di = fmaf(d.w, x, d.z);        // p_i - s_r*x
        float m  = fmaf(dr, dr, di * di);
        float r  = rcpa(m);
        float zr = dr * r;                   // Re(1/D) * sign: 1/D = conj(D)/m
        float t2 = di * r;                   // -Im(1/D)

        float4 n0 = sN0[n];
        float nr = fmaf(n0.y, x, n0.x);
        float ni = fmaf(n0.w, x, n0.z);
        k00r = fmaf(nr, zr, fmaf(ni,  t2, k00r));
        k00i = fmaf(ni, zr, fmaf(nr, -t2, k00i));

        float4 n1 = sN1[n];
        nr = fmaf(n1.y, x, n1.x);
        ni = fmaf(n1.w, x, n1.z);
        k01r = fmaf(nr, zr, fmaf(ni,  t2, k01r));
        k01i = fmaf(ni, zr, fmaf(nr, -t2, k01i));

        float4 n2 = sN2[n];
        nr = fmaf(n2.y, x, n2.x);
        ni = fmaf(n2.w, x, n2.z);
        k10r = fmaf(nr, zr, fmaf(ni,  t2, k10r));
        k10i = fmaf(ni, zr, fmaf(nr, -t2, k10i));

        float4 n3 = sN3[n];
        nr = fmaf(n3.y, x, n3.x);
        ni = fmaf(n3.w, x, n3.z);
        k11r = fmaf(nr, zr, fmaf(ni,  t2, k11r));
        k11i = fmaf(ni, zr, fmaf(nr, -t2, k11i));
    }

    // atRoots = c * (k00 - k01*k10/(1+k11)),  c = 1 + i*u
    float tr = k01r * k10r - k01i * k10i;
    float ti = k01r * k10i + k01i * k10r;
    float er = 1.0f + k11r, ei = k11i;
    float rinv = __fdividef(1.0f, er * er + ei * ei);
    float sr = (tr * er + ti * ei) * rinv;
    float si = (ti * er - tr * ei) * rinv;
    float ar = k00r - sr, ai = k00i - si;

    if (k < L) out[k] = ar - u * ai;   // Re((1+iu)*(ar + i*ai))
}

extern "C" void kernel_launch(void* const* d_in, const int* in_sizes, int n_in,
                              void* d_out, int out_size) {
    const float* Lr = (const float*)d_in[0];
    const float* Li = (const float*)d_in[1];
    const float* Pr = (const float*)d_in[2];
    const float* Pi = (const float*)d_in[3];
    const float* Qr = (const float*)d_in[4];
    const float* Qi = (const float*)d_in[5];
    const float* Br = (const float*)d_in[6];
    const float* Bi = (const float*)d_in[7];
    const float* Cr = (const float*)d_in[8];
    const float* Ci = (const float*)d_in[9];
    const float* step = (const float*)d_in[10];

    int L = out_size;  // L float32 elements = Re(atRoots)

    int threads = 256;
    int blocks = (L + threads - 1) / threads;
    s4_cauchy_kernel<<<blocks, threads>>>(Lr, Li, Pr, Pi, Qr, Qi, Br, Bi,
                                          Cr, Ci, step, (float*)d_out, L);
}

// round 12
// speedup vs baseline: 1.1376x; 1.0295x over previous
#include <cuda_runtime.h>

#define NSTATE 64
#define NPAIR  (NSTATE / 2)

__device__ __forceinline__ float rcpa(float x) {
    float r; asm("rcp.approx.f32 %0,%1;" : "=f"(r) : "f"(x)); return r;
}

// Pairwise-fused Cauchy kernel.
//   wa/(g-la) + wb/(g-lb) = (beta*g + alpha) / (g^2 - s*g + p)
// with g = i*x purely imaginary:
//   D  = (p_r + s_i*x - x^2) + i*(p_i - s_r*x)
//   N  = (a_r - b_i*x)       + i*(a_i + b_r*x)
// Per pair, packed contiguously (80 B):
//   [0] = {p_r, s_i, p_i, -s_r}
//   [1..4] = {a_r, -b_i, a_i, b_r} for ij = 00, 01, 10, 11
__global__ __launch_bounds__(128) void s4_cauchy_kernel(
    const float* __restrict__ Lr, const float* __restrict__ Li,
    const float* __restrict__ Pr, const float* __restrict__ Pi,
    const float* __restrict__ Qr, const float* __restrict__ Qi,
    const float* __restrict__ Br, const float* __restrict__ Bi,
    const float* __restrict__ Cr, const float* __restrict__ Ci,
    const float* __restrict__ step_ptr,
    float* __restrict__ out, int L)
{
    __shared__ __align__(16) float4 sP[NPAIR][5];
    __shared__ float sStep;

    const int t = threadIdx.x;
    if (t == 0) sStep = step_ptr[0];
    if (t < NPAIR) {
        const int a = 2 * t, b = 2 * t + 1;
        float lar = Lr[a], lai = Li[a], lbr = Lr[b], lbi = Li[b];

        // per-state numerators w_ij = a_i * b_j  (a0=conj C, a1=conj Q; b0=B, b1=P)
        float w[2][4][2];
        for (int sidx = 0; sidx < 2; sidx++) {
            int n = (sidx == 0) ? a : b;
            float cr = Cr[n], ci = Ci[n];
            float qr = Qr[n], qi = Qi[n];
            float br = Br[n], bi = Bi[n];
            float pr = Pr[n], pi = Pi[n];
            w[sidx][0][0] = cr * br + ci * bi;  w[sidx][0][1] = cr * bi - ci * br; // conjC*B
            w[sidx][1][0] = cr * pr + ci * pi;  w[sidx][1][1] = cr * pi - ci * pr; // conjC*P
            w[sidx][2][0] = qr * br + qi * bi;  w[sidx][2][1] = qr * bi - qi * br; // conjQ*B
            w[sidx][3][0] = qr * pr + qi * pi;  w[sidx][3][1] = qr * pi - qi * pr; // conjQ*P
        }

        // s = la + lb, p = la*lb
        float s_r = lar + lbr, s_i = lai + lbi;
        float p_r = lar * lbr - lai * lbi;
        float p_i = lar * lbi + lai * lbr;
        sP[t][0] = make_float4(p_r, s_i, p_i, -s_r);

        for (int ij = 0; ij < 4; ij++) {
            float war = w[0][ij][0], wai = w[0][ij][1];
            float wbr = w[1][ij][0], wbi = w[1][ij][1];
            // beta = wa + wb ; alpha = -(wa*lb + wb*la)
            float b_r = war + wbr, b_i = wai + wbi;
            float a_r = -(war * lbr - wai * lbi + wbr * lar - wbi * lai);
            float a_i = -(war * lbi + wai * lbr + wbr * lai + wbi * lar);
            sP[t][1 + ij] = make_float4(a_r, -b_i, a_i, b_r);
        }
    }
    __syncthreads();

    const int k = blockIdx.x * 128 + t;

    // x = gi = (2/step)*tan(pi*k/L);  c = 1 + i*u, u = tan(pi*k/L)
    const float PI = 3.14159265358979323846f;
    float sn, cs;
    sincosf(PI * ((float)k / (float)L), &sn, &cs);
    float u  = __fdividef(sn, cs);
    float x  = (2.0f / sStep) * u;
    float x2 = x * x;

    float k00r = 0.f, k00i = 0.f, k01r = 0.f, k01i = 0.f;
    float k10r = 0.f, k10i = 0.f, k11r = 0.f, k11i = 0.f;

#pragma unroll 8
    for (int n = 0; n < NPAIR; n++) {
        float4 d = sP[n][0];
        float dr = fmaf(d.y, x, d.x) - x2;   // p_r + s_i*x - x^2
        float di = fmaf(d.w, x, d.z);        // p_i - s_r*x
        float m  = fmaf(dr, dr, di * di);
        float r  = rcpa(m);
        float zr = dr * r;                   // 1/D = (dr - i*di) * r
        float t2 = di * r;

        float4 n0 = sP[n][1];
        float nr = fmaf(n0.y, x, n0.x);
        float ni = fmaf(n0.w, x, n0.z);
        k00r = fmaf(nr, zr, fmaf(ni,  t2, k00r));
        k00i = fmaf(ni, zr, fmaf(nr, -t2, k00i));

        float4 n1 = sP[n][2];
        nr = fmaf(n1.y, x, n1.x);
        ni = fmaf(n1.w, x, n1.z);
        k01r = fmaf(nr, zr, fmaf(ni,  t2, k01r));
        k01i = fmaf(ni, zr, fmaf(nr, -t2, k01i));

        float4 n2 = sP[n][3];
        nr = fmaf(n2.y, x, n2.x);
        ni = fmaf(n2.w, x, n2.z);
        k10r = fmaf(nr, zr, fmaf(ni,  t2, k10r));
        k10i = fmaf(ni, zr, fmaf(nr, -t2, k10i));

        float4 n3 = sP[n][4];
        nr = fmaf(n3.y, x, n3.x);
        ni = fmaf(n3.w, x, n3.z);
        k11r = fmaf(nr, zr, fmaf(ni,  t2, k11r));
        k11i = fmaf(ni, zr, fmaf(nr, -t2, k11i));
    }

    // atRoots = c * (k00 - k01*k10/(1+k11)),  c = 1 + i*u
    float tr = k01r * k10r - k01i * k10i;
    float ti = k01r * k10i + k01i * k10r;
    float er = 1.0f + k11r, ei = k11i;
    float rinv = __fdividef(1.0f, er * er + ei * ei);
    float sr = (tr * er + ti * ei) * rinv;
    float si = (ti * er - tr * ei) * rinv;
    float ar = k00r - sr, ai = k00i - si;

    if (k < L) out[k] = ar - u * ai;   // Re((1+iu)*(ar + i*ai))
}

extern "C" void kernel_launch(void* const* d_in, const int* in_sizes, int n_in,
                              void* d_out, int out_size) {
    const float* Lr = (const float*)d_in[0];
    const float* Li = (const float*)d_in[1];
    const float* Pr = (const float*)d_in[2];
    const float* Pi = (const float*)d_in[3];
    const float* Qr = (const float*)d_in[4];
    const float* Qi = (const float*)d_in[5];
    const float* Br = (const float*)d_in[6];
    const float* Bi = (const float*)d_in[7];
    const float* Cr = (const float*)d_in[8];
    const float* Ci = (const float*)d_in[9];
    const float* step = (const float*)d_in[10];

    int L = out_size;  // L float32 elements = Re(atRoots)

    int threads = 128;
    int blocks = (L + threads - 1) / threads;  // 1024 for L=131071
    s4_cauchy_kernel<<<blocks, threads>>>(Lr, Li, Pr, Pi, Qr, Qi, Br, Bi,
                                          Cr, Ci, step, (float*)d_out, L);
}